// round 9
// baseline (speedup 1.0000x reference)
#include <cuda_runtime.h>

namespace {

constexpr int Wd  = 512;
constexpr int Hd  = 512;
constexpr int TH  = 16;           // output rows per CTA
constexpr int VW  = 528;          // padded vbuf width (8 zero cols each side)
constexpr int NT  = 256;
constexpr int WIN = TH + 14;      // 30-row input window

__device__ __forceinline__ unsigned long long pack2(float lo, float hi) {
    unsigned long long r;
    asm("mov.b64 %0, {%1, %2};" : "=l"(r) : "f"(lo), "f"(hi));
    return r;
}
__device__ __forceinline__ void fma2(unsigned long long& d,
                                     unsigned long long a,
                                     unsigned long long b) {
    asm("fma.rn.f32x2 %0, %1, %2, %0;" : "+l"(d) : "l"(a), "l"(b));
}
__device__ __forceinline__ unsigned long long add2(unsigned long long a,
                                                   unsigned long long b) {
    unsigned long long r;
    asm("add.rn.f32x2 %0, %1, %2;" : "=l"(r) : "l"(a), "l"(b));
    return r;
}
__host__ __device__ constexpr int widx(int j) { return j < 8 ? j : 14 - j; }

union F4 {
    float4 f;
    unsigned long long u[2];
    float s[4];
};

__global__ void __launch_bounds__(NT, 3)
gauss_kernel(const float* __restrict__ x, const float* __restrict__ sigma,
             float* __restrict__ out, int C)
{
    __shared__ float vbuf[TH * VW];   // 33792 B

    const int strip = blockIdx.x;
    const int ch    = blockIdx.y;
    const int b     = blockIdx.z;
    const int tid   = threadIdx.x;
    const int r0    = strip * TH;

    // ---- zero-fill column halos early (independent of weights) ----
    if (tid < 64) {
        const int row = tid >> 2;
        const int q   = tid & 3;
        const int cc  = (q < 2) ? q * 4 : 520 + (q - 2) * 4;
        *reinterpret_cast<float4*>(&vbuf[row * VW + cc]) =
            make_float4(0.f, 0.f, 0.f, 0.f);
    }

    // ---- symmetric 1D Gaussian weights (8 distinct), packed broadcast ----
    const float sg  = sigma[b];
    const float inv = 1.0f / (2.0f * sg * sg + 1e-8f);
    float w[8];
    float s = 0.0f;
#pragma unroll
    for (int i = 0; i < 8; ++i) {
        const float a = (float)(7 - i);
        w[i] = __expf(-a * a * inv);
        s += (i < 7) ? 2.0f * w[i] : w[i];
    }
    const float rs = 1.0f / s;
    unsigned long long wp[8];
#pragma unroll
    for (int i = 0; i < 8; ++i) { w[i] *= rs; wp[i] = pack2(w[i], w[i]); }

    const size_t img = (size_t)(b * C + ch) * (Hd * Wd);
    const float* __restrict__ xp = x + img;
    float* __restrict__       op = out + img;

    // ================= Stage 1: vertical, global -> vbuf =================
    // thread: 2 cols x 16 rows; 30-row sliding input window
    {
        const int c0 = tid * 2;
        const int rbase = r0 - 7;

        unsigned long long acc[TH];
#pragma unroll
        for (int o = 0; o < TH; ++o) acc[o] = 0ull;

        if (rbase >= 0 && rbase + WIN - 1 < Hd) {
            const float* p = xp + (size_t)rbase * Wd + c0;
#pragma unroll
            for (int rr = 0; rr < WIN; ++rr) {
                const unsigned long long v =
                    *reinterpret_cast<const unsigned long long*>(p + rr * Wd);
#pragma unroll
                for (int o = 0; o < TH; ++o) {
                    const int j = rr - o;
                    if (j >= 0 && j < 15) fma2(acc[o], v, wp[widx(j)]);
                }
            }
        } else {
            const float* colp = xp + c0;
#pragma unroll
            for (int rr = 0; rr < WIN; ++rr) {
                const int gr = rbase + rr;
                if ((unsigned)gr < (unsigned)Hd) {
                    const unsigned long long v =
                        *reinterpret_cast<const unsigned long long*>(
                            colp + (size_t)gr * Wd);
#pragma unroll
                    for (int o = 0; o < TH; ++o) {
                        const int j = rr - o;
                        if (j >= 0 && j < 15) fma2(acc[o], v, wp[widx(j)]);
                    }
                }
            }
        }
#pragma unroll
        for (int o = 0; o < TH; ++o)
            *reinterpret_cast<unsigned long long*>(&vbuf[o * VW + 8 + c0]) =
                acc[o];
    }
    __syncthreads();

    // ================= Stage 2: horizontal, vbuf -> global =================
    // thread: 4-col chunk x 8 rows. Double-buffered row loads hide LDS
    // latency; taps split by parity into 4 independent fma2 chains.
    {
        const int chunk = tid & 127;
        const int rsel  = tid >> 7;
        const int gc0   = chunk * 4;
        const float* basep = &vbuf[8 + gc0];

        F4 buf[2][5];
#pragma unroll
        for (int k = 0; k < 5; ++k)
            buf[0][k].f = *reinterpret_cast<const float4*>(
                basep + rsel * VW - 8 + 4 * k);

#pragma unroll
        for (int t = 0; t < 8; ++t) {
            F4* cur = buf[t & 1];
            F4* nxt = buf[(t + 1) & 1];

            // prefetch next row's window while this row computes
            if (t < 7) {
                const float* rpn = basep + (rsel + 2 * (t + 1)) * VW;
#pragma unroll
                for (int k = 0; k < 5; ++k)
                    nxt[k].f = *reinterpret_cast<const float4*>(rpn - 8 + 4 * k);
            }

            // 4 chains: (ap0,ap1) x (odd-tap, even-tap)
            unsigned long long a0o = 0ull, a0e = 0ull;
            unsigned long long a1o = 0ull, a1e = 0ull;
#pragma unroll
            for (int sidx = 1; sidx <= 17; ++sidx) {
                unsigned long long P;
                if (sidx & 1) {
                    const int i0 = sidx, i1 = sidx + 1;
                    P = pack2(cur[i0 >> 2].s[i0 & 3], cur[i1 >> 2].s[i1 & 3]);
                } else {
                    P = cur[sidx >> 2].u[(sidx >> 1) & 1];
                }
                if (sidx <= 15) {
                    if (sidx & 1) fma2(a0o, P, wp[widx(sidx - 1)]);
                    else          fma2(a0e, P, wp[widx(sidx - 1)]);
                }
                if (sidx >= 3) {
                    if (sidx & 1) fma2(a1o, P, wp[widx(sidx - 3)]);
                    else          fma2(a1e, P, wp[widx(sidx - 3)]);
                }
            }
            const int row = rsel + 2 * t;
            *reinterpret_cast<ulonglong2*>(op + (size_t)(r0 + row) * Wd + gc0) =
                make_ulonglong2(add2(a0o, a0e), add2(a1o, a1e));
        }
    }
}

}  // namespace

extern "C" void kernel_launch(void* const* d_in, const int* in_sizes, int n_in,
                              void* d_out, int out_size) {
    const float* x     = (const float*)d_in[0];
    const float* sigma = (const float*)d_in[1];
    float* out         = (float*)d_out;

    const int B = in_sizes[1];                      // 32
    const int C = in_sizes[0] / (B * Hd * Wd);      // 3

    dim3 grid(Hd / TH, C, B);                       // 32 x 3 x 32 = 3072
    gauss_kernel<<<grid, NT>>>(x, sigma, out, C);
}

// round 10
// speedup vs baseline: 1.0012x; 1.0012x over previous
#include <cuda_runtime.h>

namespace {

constexpr int Wd  = 512;
constexpr int Hd  = 512;
constexpr int TH  = 16;           // output rows per CTA
constexpr int VW  = 528;          // padded vbuf width (8 zero cols each side)
constexpr int NT  = 256;
constexpr int WIN = TH + 14;      // 30-row input window

__device__ __forceinline__ unsigned long long pack2(float lo, float hi) {
    unsigned long long r;
    asm("mov.b64 %0, {%1, %2};" : "=l"(r) : "f"(lo), "f"(hi));
    return r;
}
__device__ __forceinline__ void fma2(unsigned long long& d,
                                     unsigned long long a,
                                     unsigned long long b) {
    asm("fma.rn.f32x2 %0, %1, %2, %0;" : "+l"(d) : "l"(a), "l"(b));
}
__host__ __device__ constexpr int widx(int j) { return j < 8 ? j : 14 - j; }

union F4 {
    float4 f;
    unsigned long long u[2];
    float s[4];
};

__global__ void __launch_bounds__(NT, 4)
gauss_kernel(const float* __restrict__ x, const float* __restrict__ sigma,
             float* __restrict__ out, int C)
{
    __shared__ float vbuf[TH * VW];   // 33792 B -> 4 CTAs/SM

    const int strip = blockIdx.x;
    const int ch    = blockIdx.y;
    const int b     = blockIdx.z;
    const int tid   = threadIdx.x;
    const int r0    = strip * TH;

    // ---- zero-fill column halos (words [0,8) and [520,528) per row) ----
    if (tid < 64) {
        const int row = tid >> 2;
        const int q   = tid & 3;
        const int cc  = (q < 2) ? q * 4 : 520 + (q - 2) * 4;
        *reinterpret_cast<float4*>(&vbuf[row * VW + cc]) =
            make_float4(0.f, 0.f, 0.f, 0.f);
    }

    // ---- symmetric 1D Gaussian weights (8 distinct), packed broadcast ----
    const float sg  = sigma[b];
    const float inv = 1.0f / (2.0f * sg * sg + 1e-8f);
    float w[8];
    float s = 0.0f;
#pragma unroll
    for (int i = 0; i < 8; ++i) {
        const float a = (float)(7 - i);
        w[i] = __expf(-a * a * inv);
        s += (i < 7) ? 2.0f * w[i] : w[i];
    }
    const float rs = 1.0f / s;
    unsigned long long wp[8];
#pragma unroll
    for (int i = 0; i < 8; ++i) { w[i] *= rs; wp[i] = pack2(w[i], w[i]); }

    const size_t img = (size_t)(b * C + ch) * (Hd * Wd);
    const float* __restrict__ xp = x + img;
    float* __restrict__       op = out + img;

    // ================= Stage 1: vertical, global -> vbuf =================
    // thread: 2 cols x 16 rows; 30-row sliding input window
    {
        const int c0 = tid * 2;
        const int rbase = r0 - 7;

        unsigned long long acc[TH];
#pragma unroll
        for (int o = 0; o < TH; ++o) acc[o] = 0ull;

        if (rbase >= 0 && rbase + WIN - 1 < Hd) {
            const float* p = xp + (size_t)rbase * Wd + c0;
#pragma unroll
            for (int rr = 0; rr < WIN; ++rr) {
                const unsigned long long v =
                    *reinterpret_cast<const unsigned long long*>(p + rr * Wd);
#pragma unroll
                for (int o = 0; o < TH; ++o) {
                    const int j = rr - o;
                    if (j >= 0 && j < 15) fma2(acc[o], v, wp[widx(j)]);
                }
            }
        } else {
            const float* colp = xp + c0;
#pragma unroll
            for (int rr = 0; rr < WIN; ++rr) {
                const int gr = rbase + rr;
                if ((unsigned)gr < (unsigned)Hd) {
                    const unsigned long long v =
                        *reinterpret_cast<const unsigned long long*>(
                            colp + (size_t)gr * Wd);
#pragma unroll
                    for (int o = 0; o < TH; ++o) {
                        const int j = rr - o;
                        if (j >= 0 && j < 15) fma2(acc[o], v, wp[widx(j)]);
                    }
                }
            }
        }
#pragma unroll
        for (int o = 0; o < TH; ++o)
            *reinterpret_cast<unsigned long long*>(&vbuf[o * VW + 8 + c0]) =
                acc[o];
    }
    __syncthreads();

    // ================= Stage 2: horizontal, vbuf -> global =================
    // thread: 8-col chunk x 4 rows. 24-float window per 8 outputs,
    // consumed directly from LDS.128 register quads (union), odd-s pairs
    // packed on the fly — no staging array (R6's spill cause).
    {
        const int chunk = tid & 63;       // 0..63 : 8-col chunk
        const int rsel  = tid >> 6;       // 0..3
        const int gc0   = chunk * 8;
        const float* basep = &vbuf[8 + gc0];

#pragma unroll
        for (int t = 0; t < 4; ++t) {
            const int row = rsel + 4 * t;
            const float* rp = basep + row * VW;

            F4 v[6];
#pragma unroll
            for (int k = 0; k < 6; ++k)
                v[k].f = *reinterpret_cast<const float4*>(rp - 8 + 4 * k);

            // acc pair p covers outputs (2p, 2p+1); tap pair at s feeds p
            // when j = s - 2p - 1 in [0,14]
            unsigned long long ap[4] = {0ull, 0ull, 0ull, 0ull};
#pragma unroll
            for (int sidx = 1; sidx <= 21; ++sidx) {
                unsigned long long P;
                if (sidx & 1) {
                    const int i0 = sidx, i1 = sidx + 1;
                    P = pack2(v[i0 >> 2].s[i0 & 3], v[i1 >> 2].s[i1 & 3]);
                } else {
                    P = v[sidx >> 2].u[(sidx >> 1) & 1];
                }
#pragma unroll
                for (int p = 0; p < 4; ++p) {
                    const int j = sidx - 2 * p - 1;   // compile-time
                    if (j >= 0 && j < 15) fma2(ap[p], P, wp[widx(j)]);
                }
            }
            float* po = op + (size_t)(r0 + row) * Wd + gc0;
            *reinterpret_cast<ulonglong2*>(po)     = make_ulonglong2(ap[0], ap[1]);
            *reinterpret_cast<ulonglong2*>(po + 4) = make_ulonglong2(ap[2], ap[3]);
        }
    }
}

}  // namespace

extern "C" void kernel_launch(void* const* d_in, const int* in_sizes, int n_in,
                              void* d_out, int out_size) {
    const float* x     = (const float*)d_in[0];
    const float* sigma = (const float*)d_in[1];
    float* out         = (float*)d_out;

    const int B = in_sizes[1];                      // 32
    const int C = in_sizes[0] / (B * Hd * Wd);      // 3

    dim3 grid(Hd / TH, C, B);                       // 32 x 3 x 32 = 3072
    gauss_kernel<<<grid, NT>>>(x, sigma, out, C);
}

// round 11
// speedup vs baseline: 1.0359x; 1.0347x over previous
#include <cuda_runtime.h>

namespace {

constexpr int Wd  = 512;
constexpr int Hd  = 512;
constexpr int TH  = 16;           // output rows per tile
constexpr int NTILE = 2;          // tiles (strips) per CTA
constexpr int VW  = 528;          // padded vbuf width (8 zero cols each side)
constexpr int NT  = 256;
constexpr int WIN = TH + 14;      // 30-row input window

__device__ __forceinline__ unsigned long long pack2(float lo, float hi) {
    unsigned long long r;
    asm("mov.b64 %0, {%1, %2};" : "=l"(r) : "f"(lo), "f"(hi));
    return r;
}
__device__ __forceinline__ void fma2(unsigned long long& d,
                                     unsigned long long a,
                                     unsigned long long b) {
    asm("fma.rn.f32x2 %0, %1, %2, %0;" : "+l"(d) : "l"(a), "l"(b));
}
__host__ __device__ constexpr int widx(int j) { return j < 8 ? j : 14 - j; }

union F4 {
    float4 f;
    unsigned long long u[2];
    float s[4];
};

__global__ void __launch_bounds__(NT, 4)
gauss_kernel(const float* __restrict__ x, const float* __restrict__ sigma,
             float* __restrict__ out, int C)
{
    __shared__ float vbuf[TH * VW];   // 33792 B -> 4 CTAs/SM

    const int spair = blockIdx.x;     // strip pair
    const int ch    = blockIdx.y;
    const int b     = blockIdx.z;
    const int tid   = threadIdx.x;

    // ---- zero-fill column halos once (stays valid across tiles) ----
    if (tid < 64) {
        const int row = tid >> 2;
        const int q   = tid & 3;
        const int cc  = (q < 2) ? q * 4 : 520 + (q - 2) * 4;
        *reinterpret_cast<float4*>(&vbuf[row * VW + cc]) =
            make_float4(0.f, 0.f, 0.f, 0.f);
    }

    // ---- symmetric 1D Gaussian weights (8 distinct), packed broadcast ----
    const float sg  = sigma[b];
    const float inv = 1.0f / (2.0f * sg * sg + 1e-8f);
    float w[8];
    float s = 0.0f;
#pragma unroll
    for (int i = 0; i < 8; ++i) {
        const float a = (float)(7 - i);
        w[i] = __expf(-a * a * inv);
        s += (i < 7) ? 2.0f * w[i] : w[i];
    }
    const float rs = 1.0f / s;
    unsigned long long wp[8];
#pragma unroll
    for (int i = 0; i < 8; ++i) { w[i] *= rs; wp[i] = pack2(w[i], w[i]); }

    const size_t img = (size_t)(b * C + ch) * (Hd * Wd);
    const float* __restrict__ xp = x + img;
    float* __restrict__       op = out + img;

#pragma unroll 1
    for (int tt = 0; tt < NTILE; ++tt) {
        const int r0 = (spair * NTILE + tt) * TH;
        if (tt > 0) __syncthreads();      // WAR: vbuf reuse between tiles

        // ================= Stage 1: vertical, global -> vbuf =================
        // thread: 2 cols x 16 rows; 30-row sliding input window
        {
            const int c0 = tid * 2;
            const int rbase = r0 - 7;

            unsigned long long acc[TH];
#pragma unroll
            for (int o = 0; o < TH; ++o) acc[o] = 0ull;

            if (rbase >= 0 && rbase + WIN - 1 < Hd) {
                const float* p = xp + (size_t)rbase * Wd + c0;
#pragma unroll
                for (int rr = 0; rr < WIN; ++rr) {
                    const unsigned long long v =
                        *reinterpret_cast<const unsigned long long*>(p + rr * Wd);
#pragma unroll
                    for (int o = 0; o < TH; ++o) {
                        const int j = rr - o;
                        if (j >= 0 && j < 15) fma2(acc[o], v, wp[widx(j)]);
                    }
                }
            } else {
                const float* colp = xp + c0;
#pragma unroll
                for (int rr = 0; rr < WIN; ++rr) {
                    const int gr = rbase + rr;
                    if ((unsigned)gr < (unsigned)Hd) {
                        const unsigned long long v =
                            *reinterpret_cast<const unsigned long long*>(
                                colp + (size_t)gr * Wd);
#pragma unroll
                        for (int o = 0; o < TH; ++o) {
                            const int j = rr - o;
                            if (j >= 0 && j < 15) fma2(acc[o], v, wp[widx(j)]);
                        }
                    }
                }
            }
#pragma unroll
            for (int o = 0; o < TH; ++o)
                *reinterpret_cast<unsigned long long*>(&vbuf[o * VW + 8 + c0]) =
                    acc[o];
        }
        __syncthreads();

        // ================= Stage 2: horizontal, vbuf -> global =================
        // thread: 4-col chunk x 8 rows. Even-s pairs direct from LDS.128
        // register pairs; 9 odd-s pairs packed on the fly.
        {
            const int chunk = tid & 127;
            const int rsel  = tid >> 7;
            const int gc0   = chunk * 4;
            const float* basep = &vbuf[8 + gc0];

#pragma unroll
            for (int t = 0; t < 8; ++t) {
                const int row = rsel + 2 * t;
                const float* rp = basep + row * VW;

                F4 v[5];
#pragma unroll
                for (int k = 0; k < 5; ++k)
                    v[k].f = *reinterpret_cast<const float4*>(rp - 8 + 4 * k);

                unsigned long long O[9];
#pragma unroll
                for (int k = 0; k < 9; ++k) {
                    const int i0 = 2 * k + 1;
                    const int i1 = 2 * k + 2;
                    O[k] = pack2(v[i0 >> 2].s[i0 & 3], v[i1 >> 2].s[i1 & 3]);
                }

                unsigned long long ap0 = 0ull, ap1 = 0ull;
#pragma unroll
                for (int sidx = 1; sidx <= 17; ++sidx) {
                    const unsigned long long P =
                        (sidx & 1) ? O[(sidx - 1) >> 1]
                                   : v[sidx >> 2].u[(sidx >> 1) & 1];
                    if (sidx <= 15) fma2(ap0, P, wp[widx(sidx - 1)]);
                    if (sidx >= 3)  fma2(ap1, P, wp[widx(sidx - 3)]);
                }
                *reinterpret_cast<ulonglong2*>(
                    op + (size_t)(r0 + row) * Wd + gc0) =
                    make_ulonglong2(ap0, ap1);
            }
        }
    }
}

}  // namespace

extern "C" void kernel_launch(void* const* d_in, const int* in_sizes, int n_in,
                              void* d_out, int out_size) {
    const float* x     = (const float*)d_in[0];
    const float* sigma = (const float*)d_in[1];
    float* out         = (float*)d_out;

    const int B = in_sizes[1];                      // 32
    const int C = in_sizes[0] / (B * Hd * Wd);      // 3

    dim3 grid(Hd / (TH * NTILE), C, B);             // 16 x 3 x 32 = 1536
    gauss_kernel<<<grid, NT>>>(x, sigma, out, C);
}

// round 12
// speedup vs baseline: 1.0955x; 1.0576x over previous
#include <cuda_runtime.h>

namespace {

constexpr int Wd  = 512;
constexpr int Hd  = 512;
constexpr int TH  = 16;           // output rows per CTA
constexpr int VW  = 528;          // padded vbuf width (8 zero cols each side)
constexpr int NT  = 256;
constexpr int WIN = TH + 14;      // 30-row input window

__device__ __forceinline__ unsigned long long pack2(float lo, float hi) {
    unsigned long long r;
    asm("mov.b64 %0, {%1, %2};" : "=l"(r) : "f"(lo), "f"(hi));
    return r;
}
__device__ __forceinline__ void fma2(unsigned long long& d,
                                     unsigned long long a,
                                     unsigned long long b) {
    asm("fma.rn.f32x2 %0, %1, %2, %0;" : "+l"(d) : "l"(a), "l"(b));
}
__host__ __device__ constexpr int widx(int j) { return j < 8 ? j : 14 - j; }

union F4 {
    float4 f;
    unsigned long long u[2];
    float s[4];
};

__global__ void __launch_bounds__(NT, 4)
gauss_kernel(const float* __restrict__ x, const float* __restrict__ sigma,
             float* __restrict__ out, int C)
{
    __shared__ float vbuf[TH * VW];   // 33792 B -> 4 CTAs/SM

    const int strip = blockIdx.x;
    const int ch    = blockIdx.y;
    const int b     = blockIdx.z;
    const int tid   = threadIdx.x;
    const int r0    = strip * TH;

    // ---- zero-fill column halos (words [0,8) and [520,528) per row) ----
    if (tid < 64) {
        const int row = tid >> 2;
        const int q   = tid & 3;
        const int cc  = (q < 2) ? q * 4 : 520 + (q - 2) * 4;
        *reinterpret_cast<float4*>(&vbuf[row * VW + cc]) =
            make_float4(0.f, 0.f, 0.f, 0.f);
    }

    // ---- symmetric 1D Gaussian weights (8 distinct), packed broadcast ----
    const float sg  = sigma[b];
    const float inv = 1.0f / (2.0f * sg * sg + 1e-8f);
    float w[8];
    float s = 0.0f;
#pragma unroll
    for (int i = 0; i < 8; ++i) {
        const float a = (float)(7 - i);
        w[i] = __expf(-a * a * inv);
        s += (i < 7) ? 2.0f * w[i] : w[i];
    }
    const float rs = 1.0f / s;
    unsigned long long wp[8];
#pragma unroll
    for (int i = 0; i < 8; ++i) { w[i] *= rs; wp[i] = pack2(w[i], w[i]); }

    const size_t img = (size_t)(b * C + ch) * (Hd * Wd);
    const float* __restrict__ xp = x + img;
    float* __restrict__       op = out + img;

    // ================= Stage 1: vertical, global -> vbuf =================
    // thread: 2 cols x 16 rows; 30-row sliding input window
    {
        const int c0 = tid * 2;
        const int rbase = r0 - 7;

        unsigned long long acc[TH];
#pragma unroll
        for (int o = 0; o < TH; ++o) acc[o] = 0ull;

        if (rbase >= 0 && rbase + WIN - 1 < Hd) {
            const float* p = xp + (size_t)rbase * Wd + c0;
#pragma unroll
            for (int rr = 0; rr < WIN; ++rr) {
                const unsigned long long v =
                    *reinterpret_cast<const unsigned long long*>(p + rr * Wd);
#pragma unroll
                for (int o = 0; o < TH; ++o) {
                    const int j = rr - o;
                    if (j >= 0 && j < 15) fma2(acc[o], v, wp[widx(j)]);
                }
            }
        } else {
            const float* colp = xp + c0;
#pragma unroll
            for (int rr = 0; rr < WIN; ++rr) {
                const int gr = rbase + rr;
                if ((unsigned)gr < (unsigned)Hd) {
                    const unsigned long long v =
                        *reinterpret_cast<const unsigned long long*>(
                            colp + (size_t)gr * Wd);
#pragma unroll
                    for (int o = 0; o < TH; ++o) {
                        const int j = rr - o;
                        if (j >= 0 && j < 15) fma2(acc[o], v, wp[widx(j)]);
                    }
                }
            }
        }
#pragma unroll
        for (int o = 0; o < TH; ++o)
            *reinterpret_cast<unsigned long long*>(&vbuf[o * VW + 8 + c0]) =
                acc[o];
    }
    __syncthreads();

    // ================= Stage 2: horizontal, vbuf -> global =================
    // thread: 4-col chunk x 8 rows. In-place rotation: v[k] is reloaded with
    // the NEXT row's quad immediately after its statically-last use in the
    // current row, so all 5 LDS per row are issued ~2 blocks ahead of their
    // consumers — LDS latency hidden with zero extra registers.
    {
        const int chunk = tid & 127;
        const int rsel  = tid >> 7;
        const int gc0   = chunk * 4;
        const float* basep = &vbuf[8 + gc0];

        F4 v[5];
#pragma unroll
        for (int k = 0; k < 5; ++k)
            v[k].f = *reinterpret_cast<const float4*>(
                basep + rsel * VW - 8 + 4 * k);

#pragma unroll
        for (int t = 0; t < 8; ++t) {
            const int row = rsel + 2 * t;
            const float* rpn = basep + (row + 2) * VW;   // next row
            unsigned long long ap0 = 0ull, ap1 = 0ull;

            // --- block A: consume v0 (pairs s=1..3) ---
            const unsigned long long O0 = pack2(v[0].s[1], v[0].s[2]);
            const unsigned long long O1 = pack2(v[0].s[3], v[1].s[0]);
            fma2(ap0, O0, wp[widx(0)]);              // s=1
            fma2(ap0, v[0].u[1], wp[widx(1)]);       // s=2
            fma2(ap0, O1, wp[widx(2)]);              // s=3
            fma2(ap1, O1, wp[widx(0)]);
            if (t < 7) v[0].f = *reinterpret_cast<const float4*>(rpn - 8);

            // --- block B: consume v1 (pairs s=4..7) ---
            const unsigned long long O2 = pack2(v[1].s[1], v[1].s[2]);
            const unsigned long long O3 = pack2(v[1].s[3], v[2].s[0]);
            fma2(ap0, v[1].u[0], wp[widx(3)]);       // s=4
            fma2(ap1, v[1].u[0], wp[widx(1)]);
            fma2(ap0, O2, wp[widx(4)]);              // s=5
            fma2(ap1, O2, wp[widx(2)]);
            fma2(ap0, v[1].u[1], wp[widx(5)]);       // s=6
            fma2(ap1, v[1].u[1], wp[widx(3)]);
            fma2(ap0, O3, wp[widx(6)]);              // s=7
            fma2(ap1, O3, wp[widx(4)]);
            if (t < 7) v[1].f = *reinterpret_cast<const float4*>(rpn - 4);

            // --- block C: consume v2 (pairs s=8..11) ---
            const unsigned long long O4 = pack2(v[2].s[1], v[2].s[2]);
            const unsigned long long O5 = pack2(v[2].s[3], v[3].s[0]);
            fma2(ap0, v[2].u[0], wp[widx(7)]);       // s=8
            fma2(ap1, v[2].u[0], wp[widx(5)]);
            fma2(ap0, O4, wp[widx(8)]);              // s=9
            fma2(ap1, O4, wp[widx(6)]);
            fma2(ap0, v[2].u[1], wp[widx(9)]);       // s=10
            fma2(ap1, v[2].u[1], wp[widx(7)]);
            fma2(ap0, O5, wp[widx(10)]);             // s=11
            fma2(ap1, O5, wp[widx(8)]);
            if (t < 7) v[2].f = *reinterpret_cast<const float4*>(rpn);

            // --- block D: consume v3 (pairs s=12..15) ---
            const unsigned long long O6 = pack2(v[3].s[1], v[3].s[2]);
            const unsigned long long O7 = pack2(v[3].s[3], v[4].s[0]);
            fma2(ap0, v[3].u[0], wp[widx(11)]);      // s=12
            fma2(ap1, v[3].u[0], wp[widx(9)]);
            fma2(ap0, O6, wp[widx(12)]);             // s=13
            fma2(ap1, O6, wp[widx(10)]);
            fma2(ap0, v[3].u[1], wp[widx(13)]);      // s=14
            fma2(ap1, v[3].u[1], wp[widx(11)]);
            fma2(ap0, O7, wp[widx(14)]);             // s=15
            fma2(ap1, O7, wp[widx(12)]);
            if (t < 7) v[3].f = *reinterpret_cast<const float4*>(rpn + 4);

            // --- block E: consume v4 (pairs s=16..17) ---
            const unsigned long long O8 = pack2(v[4].s[1], v[4].s[2]);
            fma2(ap1, v[4].u[0], wp[widx(13)]);      // s=16
            fma2(ap1, O8, wp[widx(14)]);             // s=17
            if (t < 7) v[4].f = *reinterpret_cast<const float4*>(rpn + 8);

            *reinterpret_cast<ulonglong2*>(op + (size_t)(r0 + row) * Wd + gc0) =
                make_ulonglong2(ap0, ap1);
        }
    }
}

}  // namespace

extern "C" void kernel_launch(void* const* d_in, const int* in_sizes, int n_in,
                              void* d_out, int out_size) {
    const float* x     = (const float*)d_in[0];
    const float* sigma = (const float*)d_in[1];
    float* out         = (float*)d_out;

    const int B = in_sizes[1];                      // 32
    const int C = in_sizes[0] / (B * Hd * Wd);      // 3

    dim3 grid(Hd / TH, C, B);                       // 32 x 3 x 32 = 3072
    gauss_kernel<<<grid, NT>>>(x, sigma, out, C);
}

// round 13
// speedup vs baseline: 1.1020x; 1.0059x over previous
#include <cuda_runtime.h>

namespace {

constexpr int Wd  = 512;
constexpr int Hd  = 512;
constexpr int TH  = 16;           // output rows per CTA
constexpr int VW  = 528;          // padded vbuf width (8 zero cols each side)
constexpr int NT  = 256;
constexpr int WIN = TH + 14;      // 30-row input window

__device__ __forceinline__ unsigned long long pack2(float lo, float hi) {
    unsigned long long r;
    asm("mov.b64 %0, {%1, %2};" : "=l"(r) : "f"(lo), "f"(hi));
    return r;
}
__device__ __forceinline__ void fma2(unsigned long long& d,
                                     unsigned long long a,
                                     unsigned long long b) {
    asm("fma.rn.f32x2 %0, %1, %2, %0;" : "+l"(d) : "l"(a), "l"(b));
}
__host__ __device__ constexpr int widx(int j) { return j < 8 ? j : 14 - j; }

union F4 {
    float4 f;
    unsigned long long u[2];
    float s[4];
};

__global__ void __launch_bounds__(NT, 4)
gauss_kernel(const float* __restrict__ x, const float* __restrict__ sigma,
             float* __restrict__ out, int C)
{
    __shared__ float vbuf[TH * VW];   // 33792 B -> 4 CTAs/SM

    const int strip = blockIdx.x;
    const int ch    = blockIdx.y;
    const int b     = blockIdx.z;
    const int tid   = threadIdx.x;
    const int r0    = strip * TH;

    // ---- zero-fill column halos (words [0,8) and [520,528) per row) ----
    if (tid < 64) {
        const int row = tid >> 2;
        const int q   = tid & 3;
        const int cc  = (q < 2) ? q * 4 : 520 + (q - 2) * 4;
        *reinterpret_cast<float4*>(&vbuf[row * VW + cc]) =
            make_float4(0.f, 0.f, 0.f, 0.f);
    }

    // ---- symmetric 1D Gaussian weights (8 distinct), packed broadcast ----
    const float sg  = sigma[b];
    const float inv = 1.0f / (2.0f * sg * sg + 1e-8f);
    float w[8];
    float s = 0.0f;
#pragma unroll
    for (int i = 0; i < 8; ++i) {
        const float a = (float)(7 - i);
        w[i] = __expf(-a * a * inv);
        s += (i < 7) ? 2.0f * w[i] : w[i];
    }
    const float rs = 1.0f / s;
    unsigned long long wp[8];
#pragma unroll
    for (int i = 0; i < 8; ++i) { w[i] *= rs; wp[i] = pack2(w[i], w[i]); }

    const size_t img = (size_t)(b * C + ch) * (Hd * Wd);
    const float* __restrict__ xp = x + img;
    float* __restrict__       op = out + img;

    // ================= Stage 1: vertical, global -> vbuf =================
    // thread: 2 cols x 16 rows; 30-row sliding input window
    {
        const int c0 = tid * 2;
        const int rbase = r0 - 7;

        unsigned long long acc[TH];
#pragma unroll
        for (int o = 0; o < TH; ++o) acc[o] = 0ull;

        if (rbase >= 0 && rbase + WIN - 1 < Hd) {
            const float* p = xp + (size_t)rbase * Wd + c0;
#pragma unroll
            for (int rr = 0; rr < WIN; ++rr) {
                const unsigned long long v =
                    *reinterpret_cast<const unsigned long long*>(p + rr * Wd);
#pragma unroll
                for (int o = 0; o < TH; ++o) {
                    const int j = rr - o;
                    if (j >= 0 && j < 15) fma2(acc[o], v, wp[widx(j)]);
                }
            }
        } else {
            const float* colp = xp + c0;
#pragma unroll
            for (int rr = 0; rr < WIN; ++rr) {
                const int gr = rbase + rr;
                if ((unsigned)gr < (unsigned)Hd) {
                    const unsigned long long v =
                        *reinterpret_cast<const unsigned long long*>(
                            colp + (size_t)gr * Wd);
#pragma unroll
                    for (int o = 0; o < TH; ++o) {
                        const int j = rr - o;
                        if (j >= 0 && j < 15) fma2(acc[o], v, wp[widx(j)]);
                    }
                }
            }
        }
#pragma unroll
        for (int o = 0; o < TH; ++o)
            *reinterpret_cast<unsigned long long*>(&vbuf[o * VW + 8 + c0]) =
                acc[o];
    }
    __syncthreads();

    // ================= Stage 2: horizontal, vbuf -> global =================
    // thread: 4-col chunk x 8 rows. In-place rotation: v[k] is reloaded with
    // the NEXT row's quad immediately after its statically-last use in the
    // current row, so all 5 LDS per row are issued ~2 blocks ahead of their
    // consumers — LDS latency hidden with zero extra registers.
    {
        const int chunk = tid & 127;
        const int rsel  = tid >> 7;
        const int gc0   = chunk * 4;
        const float* basep = &vbuf[8 + gc0];

        F4 v[5];
#pragma unroll
        for (int k = 0; k < 5; ++k)
            v[k].f = *reinterpret_cast<const float4*>(
                basep + rsel * VW - 8 + 4 * k);

#pragma unroll
        for (int t = 0; t < 8; ++t) {
            const int row = rsel + 2 * t;
            const float* rpn = basep + (row + 2) * VW;   // next row
            unsigned long long ap0 = 0ull, ap1 = 0ull;

            // --- block A: consume v0 (pairs s=1..3) ---
            const unsigned long long O0 = pack2(v[0].s[1], v[0].s[2]);
            const unsigned long long O1 = pack2(v[0].s[3], v[1].s[0]);
            fma2(ap0, O0, wp[widx(0)]);              // s=1
            fma2(ap0, v[0].u[1], wp[widx(1)]);       // s=2
            fma2(ap0, O1, wp[widx(2)]);              // s=3
            fma2(ap1, O1, wp[widx(0)]);
            if (t < 7) v[0].f = *reinterpret_cast<const float4*>(rpn - 8);

            // --- block B: consume v1 (pairs s=4..7) ---
            const unsigned long long O2 = pack2(v[1].s[1], v[1].s[2]);
            const unsigned long long O3 = pack2(v[1].s[3], v[2].s[0]);
            fma2(ap0, v[1].u[0], wp[widx(3)]);       // s=4
            fma2(ap1, v[1].u[0], wp[widx(1)]);
            fma2(ap0, O2, wp[widx(4)]);              // s=5
            fma2(ap1, O2, wp[widx(2)]);
            fma2(ap0, v[1].u[1], wp[widx(5)]);       // s=6
            fma2(ap1, v[1].u[1], wp[widx(3)]);
            fma2(ap0, O3, wp[widx(6)]);              // s=7
            fma2(ap1, O3, wp[widx(4)]);
            if (t < 7) v[1].f = *reinterpret_cast<const float4*>(rpn - 4);

            // --- block C: consume v2 (pairs s=8..11) ---
            const unsigned long long O4 = pack2(v[2].s[1], v[2].s[2]);
            const unsigned long long O5 = pack2(v[2].s[3], v[3].s[0]);
            fma2(ap0, v[2].u[0], wp[widx(7)]);       // s=8
            fma2(ap1, v[2].u[0], wp[widx(5)]);
            fma2(ap0, O4, wp[widx(8)]);              // s=9
            fma2(ap1, O4, wp[widx(6)]);
            fma2(ap0, v[2].u[1], wp[widx(9)]);       // s=10
            fma2(ap1, v[2].u[1], wp[widx(7)]);
            fma2(ap0, O5, wp[widx(10)]);             // s=11
            fma2(ap1, O5, wp[widx(8)]);
            if (t < 7) v[2].f = *reinterpret_cast<const float4*>(rpn);

            // --- block D: consume v3 (pairs s=12..15) ---
            const unsigned long long O6 = pack2(v[3].s[1], v[3].s[2]);
            const unsigned long long O7 = pack2(v[3].s[3], v[4].s[0]);
            fma2(ap0, v[3].u[0], wp[widx(11)]);      // s=12
            fma2(ap1, v[3].u[0], wp[widx(9)]);
            fma2(ap0, O6, wp[widx(12)]);             // s=13
            fma2(ap1, O6, wp[widx(10)]);
            fma2(ap0, v[3].u[1], wp[widx(13)]);      // s=14
            fma2(ap1, v[3].u[1], wp[widx(11)]);
            fma2(ap0, O7, wp[widx(14)]);             // s=15
            fma2(ap1, O7, wp[widx(12)]);
            if (t < 7) v[3].f = *reinterpret_cast<const float4*>(rpn + 4);

            // --- block E: consume v4 (pairs s=16..17) ---
            const unsigned long long O8 = pack2(v[4].s[1], v[4].s[2]);
            fma2(ap1, v[4].u[0], wp[widx(13)]);      // s=16
            fma2(ap1, O8, wp[widx(14)]);             // s=17
            if (t < 7) v[4].f = *reinterpret_cast<const float4*>(rpn + 8);

            *reinterpret_cast<ulonglong2*>(op + (size_t)(r0 + row) * Wd + gc0) =
                make_ulonglong2(ap0, ap1);
        }
    }
}

}  // namespace

extern "C" void kernel_launch(void* const* d_in, const int* in_sizes, int n_in,
                              void* d_out, int out_size) {
    const float* x     = (const float*)d_in[0];
    const float* sigma = (const float*)d_in[1];
    float* out         = (float*)d_out;

    const int B = in_sizes[1];                      // 32
    const int C = in_sizes[0] / (B * Hd * Wd);      // 3

    dim3 grid(Hd / TH, C, B);                       // 32 x 3 x 32 = 3072
    gauss_kernel<<<grid, NT>>>(x, sigma, out, C);
}